// round 15
// baseline (speedup 1.0000x reference)
#include <cuda_runtime.h>
#include <math.h>
#include <stdint.h>

#define Bn 16
#define Sn 512
#define Dn 768
#define Hn 8
#define DKn 96

// ======================= static scratch =======================
__device__ float g_q[Bn * Sn * Dn];
__device__ float g_kt[Bn * Dn * Sn];
__device__ float g_h0[Bn * Sn * Dn];
__device__ float g_denom[Bn * Sn];
__device__ float g_pool[Bn * 2 * Dn];
__device__ float g_gc[Bn * Dn];
__device__ float g_gate[Bn * Dn];
// packed bf16x2 hi/lo planes (uint4 for 16B alignment), pair-permuted layout
__device__ uint4 g_pa_h[8192 * 384 / 4],  g_pa_l[8192 * 384 / 4];   // A: inputs / combined
__device__ uint4 g_bw_h[5 * 768 * 384 / 4], g_bw_l[5 * 768 * 384 / 4]; // B: 5 weights
__device__ uint4 g_bx_h[16 * 768 * 256 / 4], g_bx_l[16 * 768 * 256 / 4]; // B: inputs/h0 T
__device__ uint4 g_aj_h[8192 * 256 / 4],  g_aj_l[8192 * 256 / 4];   // A: adj
__device__ uint4 g_ax_h[8192 * 384 / 4],  g_ax_l[8192 * 384 / 4];   // A: ax (bmm out)

// ======================= helpers =======================
__device__ __forceinline__ uint32_t smem_to_u32(const void* p) {
    uint32_t a;
    asm("{ .reg .u64 t; cvta.to.shared.u64 t, %1; cvt.u32.u64 %0, t; }" : "=r"(a) : "l"(p));
    return a;
}
#define CP_ASYNC16(dst, src) \
    asm volatile("cp.async.cg.shared.global [%0], [%1], 16;" :: "r"(dst), "l"(src) : "memory")

__device__ __forceinline__ uint32_t pack_bf2(float x0, float x1) {
    uint32_t r;  // lo half = x0, hi half = x1
    asm("cvt.rn.bf16x2.f32 %0, %1, %2;" : "=r"(r) : "f"(x1), "f"(x0));
    return r;
}
__device__ __forceinline__ float bf_lo(uint32_t h) { return __uint_as_float(h << 16); }
__device__ __forceinline__ float bf_hi(uint32_t h) { return __uint_as_float(h & 0xffff0000u); }
__device__ __forceinline__ void split_pair(float x0, float x1, uint32_t& h, uint32_t& l) {
    h = pack_bf2(x0, x1);
    l = pack_bf2(x0 - bf_lo(h), x1 - bf_hi(h));
}
__device__ __forceinline__ void mma_bf16(float* c, const uint32_t* a, const uint32_t* b) {
    asm volatile(
        "mma.sync.aligned.m16n8k16.row.col.f32.bf16.bf16.f32 "
        "{%0,%1,%2,%3},{%4,%5,%6,%7},{%8,%9},{%0,%1,%2,%3};"
        : "+f"(c[0]), "+f"(c[1]), "+f"(c[2]), "+f"(c[3])
        : "r"(a[0]), "r"(a[1]), "r"(a[2]), "r"(a[3]), "r"(b[0]), "r"(b[1]));
}

// ======================= pack kernels (pair-permuted: p = (q&3)*2 + (q>>2)) ==========
__global__ void packA(const float* __restrict__ src, uint32_t* __restrict__ dh,
                      uint32_t* __restrict__ dl, int K)
{
    const int KP = K >> 1;
    const int idx = blockIdx.x * 256 + threadIdx.x;
    const int m = idx / KP, qg = idx - m * KP;
    const int g = qg >> 3, qi = qg & 7;
    const float2 v = *(const float2*)(src + (long long)m * K + g * 16 + qi * 2);
    uint32_t h, l;
    split_pair(v.x, v.y, h, l);
    const int p = ((qi & 3) << 1) | (qi >> 2);
    const long long o = (long long)m * KP + g * 8 + p;
    dh[o] = h; dl[o] = l;
}

// 5-weight transpose-pack in one launch: z selects Wq,Wk,W0,W1,Wf.
__global__ void packBT5(const float* __restrict__ s0, const float* __restrict__ s1,
                        const float* __restrict__ s2, const float* __restrict__ s3,
                        const float* __restrict__ s4,
                        uint32_t* __restrict__ dh, uint32_t* __restrict__ dl,
                        long long dstride, int K, int N)
{
    __shared__ float t[16][65];
    const int z = blockIdx.z;
    const float* src = (z == 0) ? s0 : (z == 1) ? s1 : (z == 2) ? s2 : (z == 3) ? s3 : s4;
    uint32_t* oh = dh + (long long)z * dstride;
    uint32_t* ol = dl + (long long)z * dstride;
    const int n0 = blockIdx.x * 64, k0 = blockIdx.y * 16;
    const int tid = threadIdx.x;
    for (int e = tid; e < 1024; e += 256) {
        const int kk = e >> 6, nn = e & 63;
        t[kk][nn] = src[(long long)(k0 + kk) * N + n0 + nn];
    }
    __syncthreads();
    const int KP = K >> 1;
    for (int e = tid; e < 512; e += 256) {
        const int n = e >> 3, p = e & 7;
        const int q = ((p & 1) << 2) | (p >> 1);
        uint32_t h, l;
        split_pair(t[2 * q][n], t[2 * q + 1][n], h, l);
        const long long o = (long long)(n0 + n) * KP + (k0 >> 4) * 8 + p;
        oh[o] = h; ol[o] = l;
    }
}

// per-batch transpose-pack: src [z][K][N] f32 -> hi/lo [z][N][K/2] u32.
__global__ void packBTX(const float* __restrict__ s0, long long sstride,
                        uint32_t* __restrict__ dh, uint32_t* __restrict__ dl,
                        long long dstride, int K, int N)
{
    __shared__ float t[16][65];
    const int z = blockIdx.z;
    const float* src = s0 + (long long)z * sstride;
    uint32_t* oh = dh + (long long)z * dstride;
    uint32_t* ol = dl + (long long)z * dstride;
    const int n0 = blockIdx.x * 64, k0 = blockIdx.y * 16;
    const int tid = threadIdx.x;
    for (int e = tid; e < 1024; e += 256) {
        const int kk = e >> 6, nn = e & 63;
        t[kk][nn] = src[(long long)(k0 + kk) * N + n0 + nn];
    }
    __syncthreads();
    const int KP = K >> 1;
    for (int e = tid; e < 512; e += 256) {
        const int n = e >> 3, p = e & 7;
        const int q = ((p & 1) << 2) | (p >> 1);
        uint32_t h, l;
        split_pair(t[2 * q][n], t[2 * q + 1][n], h, l);
        const long long o = (long long)(n0 + n) * KP + (k0 >> 4) * 8 + p;
        oh[o] = h; ol[o] = l;
    }
}

// ======================= tensor-core GEMM (bf16 3-term split, R9-proven) =============
// TRANS (with DUAL, bz==1): output written TRANSPOSED per batch -> kT[b][D][S],
// staged through the (then-free) pipeline smem for coalesced stores.
#define PL 2048                      // u32 per plane per stage
#define NSTG 3
#define TC_SMEM (NSTG * 4 * PL * 4)  // 98304 B

#define CPPL(soff, gptr, cc) do {                                                     \
    CP_ASYNC16(sms + (soff), (const void*)((gptr) + (long long)(cc) * 16));           \
    CP_ASYNC16(sms + (soff) + 16, (const void*)((gptr) + (long long)(cc) * 16 + 4));  \
} while (0)

#define LOADC(cc, ss) do {                          \
    const uint32_t so_ = (uint32_t)(ss) * (4 * PL * 4); \
    CPPL(so_,               gAh, cc);               \
    CPPL(so_ + PL * 4,      gAl, cc);               \
    CPPL(so_ + 2 * PL * 4,  gBh, cc);               \
    CPPL(so_ + 3 * PL * 4,  gBl, cc);               \
    asm volatile("cp.async.commit_group;" ::: "memory"); \
} while (0)

template <int RELU, int DIV, int BIAS, int DUAL, int OUTPACK, int COMBINE, int TRANS>
__global__ void __launch_bounds__(256, 2) tc_gemm(
    const uint32_t* __restrict__ Ah, const uint32_t* __restrict__ Al,
    const uint32_t* __restrict__ Bh, const uint32_t* __restrict__ Bl,
    const float* __restrict__ bias, const float* __restrict__ denom,
    float* __restrict__ C, uint32_t* __restrict__ Ch, uint32_t* __restrict__ Cl,
    const uint32_t* __restrict__ Bh2, const uint32_t* __restrict__ Bl2,
    const float* __restrict__ bias2, float* __restrict__ C2,
    const float* __restrict__ h0c, const float* __restrict__ swc,
    int N, int K, long long sA, long long sB, long long sC, long long sCp)
{
    extern __shared__ uint32_t smu[];
    const uint32_t sbase = smem_to_u32(smu);
    const int tid = threadIdx.x, lane = tid & 31, wid = tid >> 5;
    const int wm = wid & 1, wn = wid >> 1;
    const int tig = lane & 3, gid = lane >> 2;
    const int row0 = blockIdx.y * 128, col0 = blockIdx.x * 128;
    const int bz = blockIdx.z;
    const int KP = K >> 1;
    const bool dotrans = TRANS && DUAL && (bz == 1);

    if (DUAL) {
        if (bz == 1) { Bh = Bh2; Bl = Bl2; bias = bias2; C = C2; }
    } else {
        Ah += bz * sA; Al += bz * sA;
        Bh += bz * sB; Bl += bz * sB;
        if (OUTPACK) { Ch += bz * sCp; Cl += bz * sCp; }
        else         { C  += bz * sC; }
    }

    const int crow = tid >> 1, ccol = (tid & 1) * 8;
    const uint32_t* gAh = Ah + (long long)(row0 + crow) * KP + ccol;
    const uint32_t* gAl = Al + (long long)(row0 + crow) * KP + ccol;
    const uint32_t* gBh = Bh + (long long)(col0 + crow) * KP + ccol;
    const uint32_t* gBl = Bl + (long long)(col0 + crow) * KP + ccol;
    const uint32_t sms = sbase + (uint32_t)(crow * 16 + ccol) * 4;

    const int nt = K >> 5;

    float acc[4][4][4];
#pragma unroll
    for (int i = 0; i < 4; i++)
#pragma unroll
        for (int j = 0; j < 4; j++)
#pragma unroll
            for (int r = 0; r < 4; r++) acc[i][j][r] = 0.f;

    LOADC(0, 0);
    LOADC(1, 1);

    for (int c = 0; c < nt; c++) {
        if (c + 1 < nt) {
            asm volatile("cp.async.wait_group 1;" ::: "memory");
        } else {
            asm volatile("cp.async.wait_group 0;" ::: "memory");
        }
        __syncthreads();
        if (c + 2 < nt) LOADC(c + 2, (c + 2) % NSTG);

        const uint32_t stof = (uint32_t)(c % NSTG) * 4 * PL;
        const uint32_t* sAh_ = smu + stof;
        const uint32_t* sAl_ = smu + stof + PL;
        const uint32_t* sBh_ = smu + stof + 2 * PL;
        const uint32_t* sBl_ = smu + stof + 3 * PL;

#pragma unroll
        for (int g = 0; g < 2; g++) {
            uint32_t ah[4][4], al[4][4];
#pragma unroll
            for (int i = 0; i < 4; i++) {
                const int m = wm * 64 + i * 16 + gid;
                const uint2 u0 = *(const uint2*)(sAh_ + m * 16 + g * 8 + 2 * tig);
                const uint2 u1 = *(const uint2*)(sAh_ + (m + 8) * 16 + g * 8 + 2 * tig);
                ah[i][0] = u0.x; ah[i][1] = u1.x; ah[i][2] = u0.y; ah[i][3] = u1.y;
                const uint2 v0 = *(const uint2*)(sAl_ + m * 16 + g * 8 + 2 * tig);
                const uint2 v1 = *(const uint2*)(sAl_ + (m + 8) * 16 + g * 8 + 2 * tig);
                al[i][0] = v0.x; al[i][1] = v1.x; al[i][2] = v0.y; al[i][3] = v1.y;
            }
#pragma unroll
            for (int j = 0; j < 4; j++) {
                const int nn = wn * 32 + j * 8 + gid;
                const uint2 bh2v = *(const uint2*)(sBh_ + nn * 16 + g * 8 + 2 * tig);
                const uint2 bl2v = *(const uint2*)(sBl_ + nn * 16 + g * 8 + 2 * tig);
                const uint32_t bhv[2] = {bh2v.x, bh2v.y};
                const uint32_t blv[2] = {bl2v.x, bl2v.y};
#pragma unroll
                for (int i = 0; i < 4; i++) mma_bf16(acc[i][j], ah[i], bhv);
#pragma unroll
                for (int i = 0; i < 4; i++) mma_bf16(acc[i][j], ah[i], blv);
#pragma unroll
                for (int i = 0; i < 4; i++) mma_bf16(acc[i][j], al[i], bhv);
            }
        }
    }

    // ---- epilogue ----
    if (dotrans) __syncthreads();   // pipeline smem is now free for the transpose stage
    float* ts = (float*)smu;        // [128 cols][129] staging (66 KB < 98 KB)

    float w0 = 0.f, w1 = 0.f;
    if (COMBINE) {
        const float s0 = swc[0], s1 = swc[1];
        const float mx = fmaxf(s0, s1);
        const float e0 = expf(s0 - mx), e1 = expf(s1 - mx);
        const float inv = 1.f / (e0 + e1);
        w0 = e0 * inv; w1 = e1 * inv;
    }
#pragma unroll
    for (int i = 0; i < 4; i++) {
        const int rl = wm * 64 + i * 16 + gid;
        const int r0 = row0 + rl;
        float inv0 = 1.f, inv1 = 1.f;
        if (DIV) { inv0 = 1.f / denom[r0]; inv1 = 1.f / denom[r0 + 8]; }
#pragma unroll
        for (int j = 0; j < 4; j++) {
            const int nc = col0 + wn * 32 + j * 8 + 2 * tig;
            float bx = 0.f, by = 0.f;
            if (BIAS) { const float2 bb = *(const float2*)(bias + nc); bx = bb.x; by = bb.y; }
            float o0 = acc[i][j][0] + bx, o1 = acc[i][j][1] + by;
            float o2 = acc[i][j][2] + bx, o3 = acc[i][j][3] + by;
            if (DIV) { o0 *= inv0; o1 *= inv0; o2 *= inv1; o3 *= inv1; }
            if (RELU) {
                o0 = fmaxf(o0, 0.f); o1 = fmaxf(o1, 0.f);
                o2 = fmaxf(o2, 0.f); o3 = fmaxf(o3, 0.f);
            }
            if (dotrans) {
                const int cl = nc - col0;
                ts[cl * 129 + rl]       = o0;
                ts[(cl + 1) * 129 + rl] = o1;
                ts[cl * 129 + rl + 8]       = o2;
                ts[(cl + 1) * 129 + rl + 8] = o3;
            } else if (OUTPACK || COMBINE) {
                if (COMBINE) {
                    const float2 ha = *(const float2*)(h0c + (long long)r0 * N + nc);
                    const float2 hb = *(const float2*)(h0c + (long long)(r0 + 8) * N + nc);
                    o0 = w0 * ha.x + w1 * o0; o1 = w0 * ha.y + w1 * o1;
                    o2 = w0 * hb.x + w1 * o2; o3 = w0 * hb.y + w1 * o3;
                }
                const int KPp = N >> 1;
                const int qg = nc >> 1, gp = qg >> 3, qi = qg & 7;
                const int p = ((qi & 3) << 1) | (qi >> 2);
                const long long p0 = (long long)r0 * KPp + gp * 8 + p;
                const long long p1 = p0 + 8LL * KPp;
                uint32_t h, l;
                split_pair(o0, o1, h, l);
                Ch[p0] = h; Cl[p0] = l;
                split_pair(o2, o3, h, l);
                Ch[p1] = h; Cl[p1] = l;
            } else {
                *(float2*)(C + (long long)r0 * N + nc) = make_float2(o0, o1);
                *(float2*)(C + (long long)(r0 + 8) * N + nc) = make_float2(o2, o3);
            }
        }
    }
    if (dotrans) {
        __syncthreads();
        const int bb = row0 >> 9, ss0 = row0 & 511;
        float* ktp = C + (long long)bb * Dn * Sn + ss0;
        for (int e = tid; e < 128 * 128; e += 256) {
            const int cc = e >> 7, rr = e & 127;
            ktp[(long long)(col0 + cc) * Sn + rr] = ts[cc * 129 + rr];
        }
    }
}

// ======================= fused attention (warp-per-q-row, barrier-free head loop) ====
__global__ void __launch_bounds__(256, 2) attn_kernel(
    const float* __restrict__ qm, const float* __restrict__ kt,
    const int* __restrict__ tok, const float* __restrict__ rel_emb,
    float* __restrict__ adj, float* __restrict__ denom,
    uint32_t* __restrict__ ajh, uint32_t* __restrict__ ajl)
{
    __shared__ __align__(16) float sQ[8][Dn];
    __shared__ __align__(16) float sQm[8][DKn];
    __shared__ float sR[8][257];
    __shared__ int sTokQ[8];

    const int tid = threadIdx.x;
    const int b = blockIdx.x >> 6;
    const int q0 = (blockIdx.x & 63) * 8;
    const long long qbase = ((long long)b * Sn + q0) * Dn;

    for (int e = tid; e < 8 * Dn; e += 256) ((float*)sQ)[e] = qm[qbase + e];
    if (tid < 8) sTokQ[tid] = tok[b * Sn + q0 + tid];
    __syncthreads();

    for (int e = tid; e < 8 * DKn; e += 256) {
        const int qq = e / DKn, d = e % DKn;
        float s = 0.f;
#pragma unroll
        for (int h = 0; h < Hn; h++) s += sQ[qq][h * DKn + d];
        sQm[qq][d] = s * 0.125f;
    }
    __syncthreads();

    for (int e = tid; e < 8 * 257; e += 256) {
        const int qq = e / 257, j = e % 257;
        const float4* rp = (const float4*)(rel_emb + j * DKn);
        const float4* qp = (const float4*)sQm[qq];
        float s = 0.f;
#pragma unroll
        for (int d4 = 0; d4 < DKn / 4; d4++) {
            float4 rv = rp[d4], qv = qp[d4];
            s += rv.x * qv.x + rv.y * qv.y + rv.z * qv.z + rv.w * qv.w;
        }
        sR[qq][j] = s;
    }
    __syncthreads();

    // warp w owns q-row q0+w; lane l owns 16 k-cols: j*128 + 4l + r (j=0..3, r=0..3)
    const int w = tid >> 5, lane = tid & 31;
    const int qrow = q0 + w;
    const float scale = 0.10206207261596577f;

    // per-lane key masks
    uint32_t kmask = 0;
#pragma unroll
    for (int j = 0; j < 4; j++) {
        const int4 tv = *(const int4*)(tok + b * Sn + j * 128 + 4 * lane);
        kmask |= (tv.x == 0 ? 1u : 0u) << (j * 4 + 0);
        kmask |= (tv.y == 0 ? 1u : 0u) << (j * 4 + 1);
        kmask |= (tv.z == 0 ? 1u : 0u) << (j * 4 + 2);
        kmask |= (tv.w == 0 ? 1u : 0u) << (j * 4 + 3);
    }

    const float* ktb = kt + (long long)b * Dn * Sn;

    float padj[4][4];
#pragma unroll
    for (int j = 0; j < 4; j++)
#pragma unroll
        for (int r = 0; r < 4; r++) padj[j][r] = 0.f;

    for (int h = 0; h < Hn; h++) {
        float sc[4][4];
#pragma unroll
        for (int j = 0; j < 4; j++)
#pragma unroll
            for (int r = 0; r < 4; r++) sc[j][r] = 0.f;

        const float* kh = ktb + (long long)h * DKn * Sn;
#pragma unroll 4
        for (int d = 0; d < DKn; d += 4) {
            const float4 qv = *(const float4*)&sQ[w][h * DKn + d];
#pragma unroll
            for (int dd = 0; dd < 4; dd++) {
                const float qd = (dd == 0) ? qv.x : (dd == 1) ? qv.y : (dd == 2) ? qv.z : qv.w;
                const float4* kr = (const float4*)(kh + (d + dd) * Sn) + lane;
#pragma unroll
                for (int j = 0; j < 4; j++) {
                    const float4 kv = kr[j * 32];
                    sc[j][0] += qd * kv.x;
                    sc[j][1] += qd * kv.y;
                    sc[j][2] += qd * kv.z;
                    sc[j][3] += qd * kv.w;
                }
            }
        }

        // rel bias + mask
        float m = -3.402823466e38f;
#pragma unroll
        for (int j = 0; j < 4; j++)
#pragma unroll
            for (int r = 0; r < 4; r++) {
                const int col = j * 128 + 4 * lane + r;
                int dist = col - qrow;
                dist = min(max(dist, -128), 128) + 128;
                float s = (sc[j][r] + sR[w][dist]) * scale;
                if (kmask & (1u << (j * 4 + r))) s = -1e9f;
                sc[j][r] = s;
                m = fmaxf(m, s);
            }
#pragma unroll
        for (int off = 16; off > 0; off >>= 1)
            m = fmaxf(m, __shfl_xor_sync(0xffffffffu, m, off));

        float sum = 0.f;
#pragma unroll
        for (int j = 0; j < 4; j++)
#pragma unroll
            for (int r = 0; r < 4; r++) {
                const float e = expf(sc[j][r] - m);
                sc[j][r] = e;
                sum += e;
            }
#pragma unroll
        for (int off = 16; off > 0; off >>= 1)
            sum += __shfl_xor_sync(0xffffffffu, sum, off);

        const float inv = 0.125f / sum;
#pragma unroll
        for (int j = 0; j < 4; j++)
#pragma unroll
            for (int r = 0; r < 4; r++) padj[j][r] += sc[j][r] * inv;
    }

    // diag -> 1, row mask, write adj + packed planes, denom (all warp-local)
    const int qz = sTokQ[w];
    float rsum = 0.f;
    const long long mrow = (long long)b * Sn + qrow;
    float* arow = adj + mrow * Sn;
    uint32_t* ajhr = ajh + mrow * (Sn / 2);
    uint32_t* ajlr = ajl + mrow * (Sn / 2);
#pragma unroll
    for (int j = 0; j < 4; j++) {
        float v[4];
#pragma unroll
        for (int r = 0; r < 4; r++) {
            float x = padj[j][r];
            const int col = j * 128 + 4 * lane + r;
            if (col == qrow) x = 1.0f;
            if (qz == 0) x = 0.0f;
            v[r] = x;
            rsum += x;
        }
        *(float4*)(arow + j * 128 + 4 * lane) = make_float4(v[0], v[1], v[2], v[3]);
        // packed pairs: qg = j*64 + 2*lane (+1)
#pragma unroll
        for (int pp = 0; pp < 2; pp++) {
            uint32_t h, l;
            split_pair(v[2 * pp], v[2 * pp + 1], h, l);
            const int qg = j * 64 + 2 * lane + pp;
            const int g = qg >> 3, qi = qg & 7;
            const int p = ((qi & 3) << 1) | (qi >> 2);
            ajhr[g * 8 + p] = h;
            ajlr[g * 8 + p] = l;
        }
    }
#pragma unroll
    for (int off = 16; off > 0; off >>= 1)
        rsum += __shfl_xor_sync(0xffffffffu, rsum, off);
    if (lane == 0) denom[mrow] = rsum + 1.0f;
}

// ======================= small kernels =======================
__global__ void pool_kernel(const float* __restrict__ x, float* __restrict__ pool)
{
    const int b = blockIdx.y;
    const int d = blockIdx.x * 128 + threadIdx.x;
    const float* xp = x + (long long)b * Sn * Dn + d;
    float sm = 0.f, mx = -3.402823466e38f;
    for (int s = 0; s < Sn; s++) {
        const float v = xp[(long long)s * Dn];
        sm += v;
        mx = fmaxf(mx, v);
    }
    pool[b * (2 * Dn) + d] = sm * (1.f / Sn);
    pool[b * (2 * Dn) + Dn + d] = mx;
}

template <int ACT>
__global__ void rowmat_kernel(const float* __restrict__ in, const float* __restrict__ W,
                              const float* __restrict__ bias, float* __restrict__ out,
                              int K, int N)
{
    __shared__ float sIn[2 * Dn];
    const int b = blockIdx.y;
    const int n = blockIdx.x * 128 + threadIdx.x;
    for (int e = threadIdx.x; e < K; e += 128) sIn[e] = in[b * K + e];
    __syncthreads();
    float acc = bias[n];
#pragma unroll 4
    for (int k = 0; k < K; k++) acc += sIn[k] * W[(long long)k * N + n];
    if (ACT) acc = 1.f / (1.f + expf(-acc));
    out[b * N + n] = acc;
}

__global__ void final_kernel(float* __restrict__ x, const float* __restrict__ gate,
                             const float* __restrict__ gc)
{
    const int i = blockIdx.x * 256 + threadIdx.x;
    const int d = i % Dn;
    const int b = i / (Sn * Dn);
    x[i] += gate[b * Dn + d] * gc[b * Dn + d];
}

// ======================= launch =======================
extern "C" void kernel_launch(void* const* d_in, const int* in_sizes, int n_in,
                              void* d_out, int out_size)
{
    int o = (n_in >= 3 && in_sizes[2] == 1) ? 1 : 0;
    const float* inputs = (const float*)d_in[0];
    const int*   tok    = (const int*)d_in[1];
    const float* Wq  = (const float*)d_in[2 + o];
    const float* bq  = (const float*)d_in[3 + o];
    const float* Wk  = (const float*)d_in[4 + o];
    const float* bk  = (const float*)d_in[5 + o];
    const float* rel = (const float*)d_in[6 + o];
    const float* W0  = (const float*)d_in[7 + o];
    const float* b0  = (const float*)d_in[8 + o];
    const float* W1  = (const float*)d_in[9 + o];
    const float* b1  = (const float*)d_in[10 + o];
    const float* scw = (const float*)d_in[11 + o];
    const float* Wf  = (const float*)d_in[12 + o];
    const float* bf  = (const float*)d_in[13 + o];
    const float* Wfc = (const float*)d_in[14 + o];
    const float* bfc = (const float*)d_in[15 + o];
    const float* Wg  = (const float*)d_in[16 + o];
    const float* bg  = (const float*)d_in[17 + o];

    float* out = (float*)d_out;                      // (B,S,D)
    float* adj = out + (size_t)Bn * Sn * Dn;         // (B,S,S)

    float *q, *kt, *h0, *den, *pool, *gc, *gate;
    uint32_t *pah, *pal, *bwh, *bwl, *bxh, *bxl, *ajh, *ajl, *axh, *axl;
    cudaGetSymbolAddress((void**)&q, g_q);
    cudaGetSymbolAddress((void**)&kt, g_kt);
    cudaGetSymbolAddress((void**)&h0, g_h0);
    cudaGetSymbolAddress((void**)&den, g_denom);
    cudaGetSymbolAddress((void**)&pool, g_pool);
    cudaGetSymbolAddress((void**)&gc, g_gc);
    cudaGetSymbolAddress((void**)&gate, g_gate);
    cudaGetSymbolAddress((void**)&pah, g_pa_h);
    cudaGetSymbolAddress((void**)&pal, g_pa_l);
    cudaGetSymbolAddress((void**)&bwh, g_bw_h);
    cudaGetSymbolAddress((void**)&bwl, g_bw_l);
    cudaGetSymbolAddress((void**)&bxh, g_bx_h);
    cudaGetSymbolAddress((void**)&bxl, g_bx_l);
    cudaGetSymbolAddress((void**)&ajh, g_aj_h);
    cudaGetSymbolAddress((void**)&ajl, g_aj_l);
    cudaGetSymbolAddress((void**)&axh, g_ax_h);
    cudaGetSymbolAddress((void**)&axl, g_ax_l);

    cudaFuncSetAttribute(tc_gemm<0, 0, 1, 1, 0, 0, 1>, cudaFuncAttributeMaxDynamicSharedMemorySize, TC_SMEM);
    cudaFuncSetAttribute(tc_gemm<0, 0, 0, 0, 1, 0, 0>, cudaFuncAttributeMaxDynamicSharedMemorySize, TC_SMEM);
    cudaFuncSetAttribute(tc_gemm<1, 1, 1, 0, 0, 0, 0>, cudaFuncAttributeMaxDynamicSharedMemorySize, TC_SMEM);
    cudaFuncSetAttribute(tc_gemm<1, 1, 1, 0, 0, 1, 0>, cudaFuncAttributeMaxDynamicSharedMemorySize, TC_SMEM);
    cudaFuncSetAttribute(tc_gemm<0, 0, 1, 0, 0, 0, 0>, cudaFuncAttributeMaxDynamicSharedMemorySize, TC_SMEM);

    const long long WOFF = 768LL * 384;              // per-weight packed plane stride
    const dim3 gFlat(Dn / 128, (Bn * Sn) / 128, 1);  // 6 x 64
    const dim3 gQK(Dn / 128, (Bn * Sn) / 128, 2);
    const dim3 gBmm(Dn / 128, Sn / 128, Bn);         // 6 x 4 x 16

    // [1] pack A(inputs) for projections
    packA<<<(8192 * 384) / 256, 256>>>(inputs, pah, pal, Dn);
    // [2] pack B: all 5 weights in one launch (Wq, Wk, W0, W1, Wf)
    packBT5<<<dim3(Dn / 64, Dn / 16, 5), 256>>>(Wq, Wk, W0, W1, Wf,
                                                bwh, bwl, WOFF, Dn, Dn);
    // [3] QK projections (dual); K output written TRANSPOSED -> kT directly
    tc_gemm<0, 0, 1, 1, 0, 0, 1><<<gQK, 256, TC_SMEM>>>(
        pah, pal, bwh, bwl, bq, nullptr, q, nullptr, nullptr,
        bwh + WOFF, bwl + WOFF, bk, kt, nullptr, nullptr, Dn, Dn, 0, 0, 0, 0);
    // [4] fused attention (warp-per-row) -> adj + packed planes, denom  (ncu slot)
    attn_kernel<<<Bn * (Sn / 8), 256>>>(q, kt, tok, rel, adj, den, ajh, ajl);
    // [5] pack B: inputs transposed per batch (for bmm0)
    packBTX<<<dim3(Dn / 64, Sn / 16, Bn), 256>>>(inputs, (long long)Sn * Dn,
                                                 bxh, bxl, 768LL * 256, Sn, Dn);
    // [6] bmm0: ax = adj @ inputs  (packed output)
    tc_gemm<0, 0, 0, 0, 1, 0, 0><<<gBmm, 256, TC_SMEM>>>(
        ajh, ajl, bxh, bxl, nullptr, nullptr, nullptr, axh, axl,
        nullptr, nullptr, nullptr, nullptr, nullptr, nullptr, Dn, Sn,
        512LL * 256, 768LL * 256, 0, 512LL * 384);
    // [7] wgemm0: h0 = relu((ax@W0+b0)/den)
    tc_gemm<1, 1, 1, 0, 0, 0, 0><<<gFlat, 256, TC_SMEM>>>(
        axh, axl, bwh + 2 * WOFF, bwl + 2 * WOFF, b0, den, h0, nullptr, nullptr,
        nullptr, nullptr, nullptr, nullptr, nullptr, nullptr, Dn, Dn, 0, 0, 0, 0);
    // [8] pack B: h0 transposed per batch (for bmm1)
    packBTX<<<dim3(Dn / 64, Sn / 16, Bn), 256>>>(h0, (long long)Sn * Dn,
                                                 bxh, bxl, 768LL * 256, Sn, Dn);
    // [9] bmm1
    tc_gemm<0, 0, 0, 0, 1, 0, 0><<<gBmm, 256, TC_SMEM>>>(
        ajh, ajl, bxh, bxl, nullptr, nullptr, nullptr, axh, axl,
        nullptr, nullptr, nullptr, nullptr, nullptr, nullptr, Dn, Sn,
        512LL * 256, 768LL * 256, 0, 512LL * 384);
    // [10] wgemm1 + fused combine -> packed combined planes
    tc_gemm<1, 1, 1, 0, 0, 1, 0><<<gFlat, 256, TC_SMEM>>>(
        axh, axl, bwh + 3 * WOFF, bwl + 3 * WOFF, b1, den, nullptr, pah, pal,
        nullptr, nullptr, nullptr, nullptr, h0, scw, Dn, Dn, 0, 0, 0, 0);
    // [11] Wf GEMM -> out
    tc_gemm<0, 0, 1, 0, 0, 0, 0><<<gFlat, 256, TC_SMEM>>>(
        pah, pal, bwh + 4 * WOFF, bwl + 4 * WOFF, bf, nullptr, out, nullptr, nullptr,
        nullptr, nullptr, nullptr, nullptr, nullptr, nullptr, Dn, Dn, 0, 0, 0, 0);

    // global context gating
    pool_kernel<<<dim3(Dn / 128, Bn), 128>>>(out, pool);
    rowmat_kernel<0><<<dim3(Dn / 128, Bn), 128>>>(pool, Wfc, bfc, gc, 2 * Dn, Dn);
    rowmat_kernel<1><<<dim3(Dn / 128, Bn), 128>>>(gc, Wg, bg, gate, Dn, Dn);
    final_kernel<<<(Bn * Sn * Dn) / 256, 256>>>(out, gate, gc);
}

// round 16
// speedup vs baseline: 1.1391x; 1.1391x over previous
#include <cuda_runtime.h>
#include <math.h>
#include <stdint.h>

#define Bn 16
#define Sn 512
#define Dn 768
#define Hn 8
#define DKn 96

// ======================= static scratch =======================
__device__ float g_q[Bn * Sn * Dn];
__device__ float g_kt[Bn * Dn * Sn];
__device__ float g_h0[Bn * Sn * Dn];
__device__ float g_denom[Bn * Sn];
__device__ float g_pool[Bn * 2 * Dn];
__device__ float g_gc[Bn * Dn];
__device__ float g_gate[Bn * Dn];
// packed bf16x2 hi/lo planes (uint4 for 16B alignment), pair-permuted layout
__device__ uint4 g_pa_h[8192 * 384 / 4],  g_pa_l[8192 * 384 / 4];   // A: inputs / combined
__device__ uint4 g_bw_h[5 * 768 * 384 / 4], g_bw_l[5 * 768 * 384 / 4]; // B: 5 weights
__device__ uint4 g_bx_h[16 * 768 * 256 / 4], g_bx_l[16 * 768 * 256 / 4]; // B: inputs/h0 T
__device__ uint4 g_aj_h[8192 * 256 / 4],  g_aj_l[8192 * 256 / 4];   // A: adj
__device__ uint4 g_ax_h[8192 * 384 / 4],  g_ax_l[8192 * 384 / 4];   // A: ax (bmm out)

// ======================= helpers =======================
__device__ __forceinline__ uint32_t smem_to_u32(const void* p) {
    uint32_t a;
    asm("{ .reg .u64 t; cvta.to.shared.u64 t, %1; cvt.u32.u64 %0, t; }" : "=r"(a) : "l"(p));
    return a;
}
#define CP_ASYNC16(dst, src) \
    asm volatile("cp.async.cg.shared.global [%0], [%1], 16;" :: "r"(dst), "l"(src) : "memory")

__device__ __forceinline__ uint32_t pack_bf2(float x0, float x1) {
    uint32_t r;  // lo half = x0, hi half = x1
    asm("cvt.rn.bf16x2.f32 %0, %1, %2;" : "=r"(r) : "f"(x1), "f"(x0));
    return r;
}
__device__ __forceinline__ float bf_lo(uint32_t h) { return __uint_as_float(h << 16); }
__device__ __forceinline__ float bf_hi(uint32_t h) { return __uint_as_float(h & 0xffff0000u); }
__device__ __forceinline__ void split_pair(float x0, float x1, uint32_t& h, uint32_t& l) {
    h = pack_bf2(x0, x1);
    l = pack_bf2(x0 - bf_lo(h), x1 - bf_hi(h));
}
__device__ __forceinline__ void mma_bf16(float* c, const uint32_t* a, const uint32_t* b) {
    asm volatile(
        "mma.sync.aligned.m16n8k16.row.col.f32.bf16.bf16.f32 "
        "{%0,%1,%2,%3},{%4,%5,%6,%7},{%8,%9},{%0,%1,%2,%3};"
        : "+f"(c[0]), "+f"(c[1]), "+f"(c[2]), "+f"(c[3])
        : "r"(a[0]), "r"(a[1]), "r"(a[2]), "r"(a[3]), "r"(b[0]), "r"(b[1]));
}

// ======================= pack kernels (pair-permuted: p = (q&3)*2 + (q>>2)) ==========
__global__ void packA(const float* __restrict__ src, uint32_t* __restrict__ dh,
                      uint32_t* __restrict__ dl, int K)
{
    const int KP = K >> 1;
    const int idx = blockIdx.x * 256 + threadIdx.x;
    const int m = idx / KP, qg = idx - m * KP;
    const int g = qg >> 3, qi = qg & 7;
    const float2 v = *(const float2*)(src + (long long)m * K + g * 16 + qi * 2);
    uint32_t h, l;
    split_pair(v.x, v.y, h, l);
    const int p = ((qi & 3) << 1) | (qi >> 2);
    const long long o = (long long)m * KP + g * 8 + p;
    dh[o] = h; dl[o] = l;
}

// 5-weight transpose-pack in one launch: z selects Wq,Wk,W0,W1,Wf.
__global__ void packBT5(const float* __restrict__ s0, const float* __restrict__ s1,
                        const float* __restrict__ s2, const float* __restrict__ s3,
                        const float* __restrict__ s4,
                        uint32_t* __restrict__ dh, uint32_t* __restrict__ dl,
                        long long dstride, int K, int N)
{
    __shared__ float t[16][65];
    const int z = blockIdx.z;
    const float* src = (z == 0) ? s0 : (z == 1) ? s1 : (z == 2) ? s2 : (z == 3) ? s3 : s4;
    uint32_t* oh = dh + (long long)z * dstride;
    uint32_t* ol = dl + (long long)z * dstride;
    const int n0 = blockIdx.x * 64, k0 = blockIdx.y * 16;
    const int tid = threadIdx.x;
    for (int e = tid; e < 1024; e += 256) {
        const int kk = e >> 6, nn = e & 63;
        t[kk][nn] = src[(long long)(k0 + kk) * N + n0 + nn];
    }
    __syncthreads();
    const int KP = K >> 1;
    for (int e = tid; e < 512; e += 256) {
        const int n = e >> 3, p = e & 7;
        const int q = ((p & 1) << 2) | (p >> 1);
        uint32_t h, l;
        split_pair(t[2 * q][n], t[2 * q + 1][n], h, l);
        const long long o = (long long)(n0 + n) * KP + (k0 >> 4) * 8 + p;
        oh[o] = h; ol[o] = l;
    }
}

// per-batch transpose-pack: src [z][K][N] f32 -> hi/lo [z][N][K/2] u32.
__global__ void packBTX(const float* __restrict__ s0, long long sstride,
                        uint32_t* __restrict__ dh, uint32_t* __restrict__ dl,
                        long long dstride, int K, int N)
{
    __shared__ float t[16][65];
    const int z = blockIdx.z;
    const float* src = s0 + (long long)z * sstride;
    uint32_t* oh = dh + (long long)z * dstride;
    uint32_t* ol = dl + (long long)z * dstride;
    const int n0 = blockIdx.x * 64, k0 = blockIdx.y * 16;
    const int tid = threadIdx.x;
    for (int e = tid; e < 1024; e += 256) {
        const int kk = e >> 6, nn = e & 63;
        t[kk][nn] = src[(long long)(k0 + kk) * N + n0 + nn];
    }
    __syncthreads();
    const int KP = K >> 1;
    for (int e = tid; e < 512; e += 256) {
        const int n = e >> 3, p = e & 7;
        const int q = ((p & 1) << 2) | (p >> 1);
        uint32_t h, l;
        split_pair(t[2 * q][n], t[2 * q + 1][n], h, l);
        const long long o = (long long)(n0 + n) * KP + (k0 >> 4) * 8 + p;
        oh[o] = h; ol[o] = l;
    }
}

// ======================= tensor-core GEMM (bf16 3-term split, R9-proven) =============
// TRANS (with DUAL, bz==1): output written TRANSPOSED per batch -> kT[b][D][S],
// staged through the (then-free) pipeline smem for coalesced stores.
#define PL 2048                      // u32 per plane per stage
#define NSTG 3
#define TC_SMEM (NSTG * 4 * PL * 4)  // 98304 B

#define CPPL(soff, gptr, cc) do {                                                     \
    CP_ASYNC16(sms + (soff), (const void*)((gptr) + (long long)(cc) * 16));           \
    CP_ASYNC16(sms + (soff) + 16, (const void*)((gptr) + (long long)(cc) * 16 + 4));  \
} while (0)

#define LOADC(cc, ss) do {                          \
    const uint32_t so_ = (uint32_t)(ss) * (4 * PL * 4); \
    CPPL(so_,               gAh, cc);               \
    CPPL(so_ + PL * 4,      gAl, cc);               \
    CPPL(so_ + 2 * PL * 4,  gBh, cc);               \
    CPPL(so_ + 3 * PL * 4,  gBl, cc);               \
    asm volatile("cp.async.commit_group;" ::: "memory"); \
} while (0)

template <int RELU, int DIV, int BIAS, int DUAL, int OUTPACK, int COMBINE, int TRANS>
__global__ void __launch_bounds__(256, 2) tc_gemm(
    const uint32_t* __restrict__ Ah, const uint32_t* __restrict__ Al,
    const uint32_t* __restrict__ Bh, const uint32_t* __restrict__ Bl,
    const float* __restrict__ bias, const float* __restrict__ denom,
    float* __restrict__ C, uint32_t* __restrict__ Ch, uint32_t* __restrict__ Cl,
    const uint32_t* __restrict__ Bh2, const uint32_t* __restrict__ Bl2,
    const float* __restrict__ bias2, float* __restrict__ C2,
    const float* __restrict__ h0c, const float* __restrict__ swc,
    int N, int K, long long sA, long long sB, long long sC, long long sCp)
{
    extern __shared__ uint32_t smu[];
    const uint32_t sbase = smem_to_u32(smu);
    const int tid = threadIdx.x, lane = tid & 31, wid = tid >> 5;
    const int wm = wid & 1, wn = wid >> 1;
    const int tig = lane & 3, gid = lane >> 2;
    const int row0 = blockIdx.y * 128, col0 = blockIdx.x * 128;
    const int bz = blockIdx.z;
    const int KP = K >> 1;
    const bool dotrans = TRANS && DUAL && (bz == 1);

    if (DUAL) {
        if (bz == 1) { Bh = Bh2; Bl = Bl2; bias = bias2; C = C2; }
    } else {
        Ah += bz * sA; Al += bz * sA;
        Bh += bz * sB; Bl += bz * sB;
        if (OUTPACK) { Ch += bz * sCp; Cl += bz * sCp; }
        else         { C  += bz * sC; }
    }

    const int crow = tid >> 1, ccol = (tid & 1) * 8;
    const uint32_t* gAh = Ah + (long long)(row0 + crow) * KP + ccol;
    const uint32_t* gAl = Al + (long long)(row0 + crow) * KP + ccol;
    const uint32_t* gBh = Bh + (long long)(col0 + crow) * KP + ccol;
    const uint32_t* gBl = Bl + (long long)(col0 + crow) * KP + ccol;
    const uint32_t sms = sbase + (uint32_t)(crow * 16 + ccol) * 4;

    const int nt = K >> 5;

    float acc[4][4][4];
#pragma unroll
    for (int i = 0; i < 4; i++)
#pragma unroll
        for (int j = 0; j < 4; j++)
#pragma unroll
            for (int r = 0; r < 4; r++) acc[i][j][r] = 0.f;

    LOADC(0, 0);
    LOADC(1, 1);

    for (int c = 0; c < nt; c++) {
        if (c + 1 < nt) {
            asm volatile("cp.async.wait_group 1;" ::: "memory");
        } else {
            asm volatile("cp.async.wait_group 0;" ::: "memory");
        }
        __syncthreads();
        if (c + 2 < nt) LOADC(c + 2, (c + 2) % NSTG);

        const uint32_t stof = (uint32_t)(c % NSTG) * 4 * PL;
        const uint32_t* sAh_ = smu + stof;
        const uint32_t* sAl_ = smu + stof + PL;
        const uint32_t* sBh_ = smu + stof + 2 * PL;
        const uint32_t* sBl_ = smu + stof + 3 * PL;

#pragma unroll
        for (int g = 0; g < 2; g++) {
            uint32_t ah[4][4], al[4][4];
#pragma unroll
            for (int i = 0; i < 4; i++) {
                const int m = wm * 64 + i * 16 + gid;
                const uint2 u0 = *(const uint2*)(sAh_ + m * 16 + g * 8 + 2 * tig);
                const uint2 u1 = *(const uint2*)(sAh_ + (m + 8) * 16 + g * 8 + 2 * tig);
                ah[i][0] = u0.x; ah[i][1] = u1.x; ah[i][2] = u0.y; ah[i][3] = u1.y;
                const uint2 v0 = *(const uint2*)(sAl_ + m * 16 + g * 8 + 2 * tig);
                const uint2 v1 = *(const uint2*)(sAl_ + (m + 8) * 16 + g * 8 + 2 * tig);
                al[i][0] = v0.x; al[i][1] = v1.x; al[i][2] = v0.y; al[i][3] = v1.y;
            }
#pragma unroll
            for (int j = 0; j < 4; j++) {
                const int nn = wn * 32 + j * 8 + gid;
                const uint2 bh2v = *(const uint2*)(sBh_ + nn * 16 + g * 8 + 2 * tig);
                const uint2 bl2v = *(const uint2*)(sBl_ + nn * 16 + g * 8 + 2 * tig);
                const uint32_t bhv[2] = {bh2v.x, bh2v.y};
                const uint32_t blv[2] = {bl2v.x, bl2v.y};
#pragma unroll
                for (int i = 0; i < 4; i++) mma_bf16(acc[i][j], ah[i], bhv);
#pragma unroll
                for (int i = 0; i < 4; i++) mma_bf16(acc[i][j], ah[i], blv);
#pragma unroll
                for (int i = 0; i < 4; i++) mma_bf16(acc[i][j], al[i], bhv);
            }
        }
    }

    // ---- epilogue ----
    if (dotrans) __syncthreads();   // pipeline smem is now free for the transpose stage
    float* ts = (float*)smu;        // [128 cols][129] staging (66 KB < 98 KB)

    float w0 = 0.f, w1 = 0.f;
    if (COMBINE) {
        const float s0 = swc[0], s1 = swc[1];
        const float mx = fmaxf(s0, s1);
        const float e0 = expf(s0 - mx), e1 = expf(s1 - mx);
        const float inv = 1.f / (e0 + e1);
        w0 = e0 * inv; w1 = e1 * inv;
    }
#pragma unroll
    for (int i = 0; i < 4; i++) {
        const int rl = wm * 64 + i * 16 + gid;
        const int r0 = row0 + rl;
        float inv0 = 1.f, inv1 = 1.f;
        if (DIV) { inv0 = 1.f / denom[r0]; inv1 = 1.f / denom[r0 + 8]; }
#pragma unroll
        for (int j = 0; j < 4; j++) {
            const int nc = col0 + wn * 32 + j * 8 + 2 * tig;
            float bx = 0.f, by = 0.f;
            if (BIAS) { const float2 bb = *(const float2*)(bias + nc); bx = bb.x; by = bb.y; }
            float o0 = acc[i][j][0] + bx, o1 = acc[i][j][1] + by;
            float o2 = acc[i][j][2] + bx, o3 = acc[i][j][3] + by;
            if (DIV) { o0 *= inv0; o1 *= inv0; o2 *= inv1; o3 *= inv1; }
            if (RELU) {
                o0 = fmaxf(o0, 0.f); o1 = fmaxf(o1, 0.f);
                o2 = fmaxf(o2, 0.f); o3 = fmaxf(o3, 0.f);
            }
            if (dotrans) {
                const int cl = nc - col0;
                ts[cl * 129 + rl]       = o0;
                ts[(cl + 1) * 129 + rl] = o1;
                ts[cl * 129 + rl + 8]       = o2;
                ts[(cl + 1) * 129 + rl + 8] = o3;
            } else if (OUTPACK || COMBINE) {
                if (COMBINE) {
                    const float2 ha = *(const float2*)(h0c + (long long)r0 * N + nc);
                    const float2 hb = *(const float2*)(h0c + (long long)(r0 + 8) * N + nc);
                    o0 = w0 * ha.x + w1 * o0; o1 = w0 * ha.y + w1 * o1;
                    o2 = w0 * hb.x + w1 * o2; o3 = w0 * hb.y + w1 * o3;
                }
                const int KPp = N >> 1;
                const int qg = nc >> 1, gp = qg >> 3, qi = qg & 7;
                const int p = ((qi & 3) << 1) | (qi >> 2);
                const long long p0 = (long long)r0 * KPp + gp * 8 + p;
                const long long p1 = p0 + 8LL * KPp;
                uint32_t h, l;
                split_pair(o0, o1, h, l);
                Ch[p0] = h; Cl[p0] = l;
                split_pair(o2, o3, h, l);
                Ch[p1] = h; Cl[p1] = l;
            } else {
                *(float2*)(C + (long long)r0 * N + nc) = make_float2(o0, o1);
                *(float2*)(C + (long long)(r0 + 8) * N + nc) = make_float2(o2, o3);
            }
        }
    }
    if (dotrans) {
        __syncthreads();
        const int bb = row0 >> 9, ss0 = row0 & 511;
        float* ktp = C + (long long)bb * Dn * Sn + ss0;
        for (int e = tid; e < 128 * 128; e += 256) {
            const int cc = e >> 7, rr = e & 127;
            ktp[(long long)(col0 + cc) * Sn + rr] = ts[cc * 129 + rr];
        }
    }
}

// ======================= fused attention (R13-proven: kT coalesced, 256 thr) =========
__global__ void __launch_bounds__(256, 2) attn_kernel(
    const float* __restrict__ qm, const float* __restrict__ kt,
    const int* __restrict__ tok, const float* __restrict__ rel_emb,
    float* __restrict__ adj, float* __restrict__ denom,
    uint32_t* __restrict__ ajh, uint32_t* __restrict__ ajl)
{
    __shared__ __align__(16) float sQ[8][Dn];
    __shared__ __align__(16) float sQm[8][DKn];
    __shared__ float sR[8][257];
    __shared__ float sRed[8][8];
    __shared__ float sB[8];
    __shared__ int sTokQ[8];

    const int tid = threadIdx.x;
    const int b = blockIdx.x >> 6;
    const int q0 = (blockIdx.x & 63) * 8;
    const long long qbase = ((long long)b * Sn + q0) * Dn;

    for (int e = tid; e < 8 * Dn; e += 256) ((float*)sQ)[e] = qm[qbase + e];
    if (tid < 8) sTokQ[tid] = tok[b * Sn + q0 + tid];
    __syncthreads();

    for (int e = tid; e < 8 * DKn; e += 256) {
        const int qq = e / DKn, d = e % DKn;
        float s = 0.f;
#pragma unroll
        for (int h = 0; h < Hn; h++) s += sQ[qq][h * DKn + d];
        sQm[qq][d] = s * 0.125f;
    }
    __syncthreads();

    for (int e = tid; e < 8 * 257; e += 256) {
        const int qq = e / 257, j = e % 257;
        const float4* rp = (const float4*)(rel_emb + j * DKn);
        const float4* qp = (const float4*)sQm[qq];
        float s = 0.f;
#pragma unroll
        for (int d4 = 0; d4 < DKn / 4; d4++) {
            float4 rv = rp[d4], qv = qp[d4];
            s += rv.x * qv.x + rv.y * qv.y + rv.z * qv.z + rv.w * qv.w;
        }
        sR[qq][j] = s;
    }
    __syncthreads();

    const int k0c = 2 * tid, k1c = 2 * tid + 1;
    const int2 tk = *(const int2*)(tok + b * Sn + k0c);
    const bool kz0 = (tk.x == 0), kz1 = (tk.y == 0);
    const float2* ktb = (const float2*)(kt + (long long)b * Dn * Sn) + tid;
    const float scale = 0.10206207261596577f;
    const int lane = tid & 31, wid = tid >> 5;

    float padj0[8], padj1[8];
#pragma unroll
    for (int qq = 0; qq < 8; qq++) { padj0[qq] = 0.f; padj1[qq] = 0.f; }

    for (int h = 0; h < Hn; h++) {
        float sc0[8], sc1[8];
#pragma unroll
        for (int qq = 0; qq < 8; qq++) { sc0[qq] = 0.f; sc1[qq] = 0.f; }
        const float2* kh = ktb + (long long)h * DKn * (Sn / 2);
#pragma unroll
        for (int d = 0; d < DKn; d += 4) {
            const float2 kv0 = kh[(d + 0) * (Sn / 2)];
            const float2 kv1 = kh[(d + 1) * (Sn / 2)];
            const float2 kv2 = kh[(d + 2) * (Sn / 2)];
            const float2 kv3 = kh[(d + 3) * (Sn / 2)];
#pragma unroll
            for (int qq = 0; qq < 8; qq++) {
                const float4 qv = *(const float4*)&sQ[qq][h * DKn + d];
                sc0[qq] += qv.x * kv0.x + qv.y * kv1.x + qv.z * kv2.x + qv.w * kv3.x;
                sc1[qq] += qv.x * kv0.y + qv.y * kv1.y + qv.z * kv2.y + qv.w * kv3.y;
            }
        }
#pragma unroll
        for (int qq = 0; qq < 8; qq++) {
            int d0 = k0c - (q0 + qq);
            d0 = min(max(d0, -128), 128) + 128;
            int d1 = k1c - (q0 + qq);
            d1 = min(max(d1, -128), 128) + 128;
            const float s0 = (sc0[qq] + sR[qq][d0]) * scale;
            const float s1 = (sc1[qq] + sR[qq][d1]) * scale;
            sc0[qq] = kz0 ? -1e9f : s0;
            sc1[qq] = kz1 ? -1e9f : s1;
        }
        float red[8];
#pragma unroll
        for (int qq = 0; qq < 8; qq++) red[qq] = fmaxf(sc0[qq], sc1[qq]);
#pragma unroll
        for (int off = 16; off > 0; off >>= 1)
#pragma unroll
            for (int qq = 0; qq < 8; qq++)
                red[qq] = fmaxf(red[qq], __shfl_xor_sync(0xffffffffu, red[qq], off));
        if (lane == 0)
#pragma unroll
            for (int qq = 0; qq < 8; qq++) sRed[wid][qq] = red[qq];
        __syncthreads();
        if (tid < 8) {
            float v = sRed[0][tid];
#pragma unroll
            for (int w = 1; w < 8; w++) v = fmaxf(v, sRed[w][tid]);
            sB[tid] = v;
        }
        __syncthreads();
        float ex0[8], ex1[8];
#pragma unroll
        for (int qq = 0; qq < 8; qq++) {
            ex0[qq] = expf(sc0[qq] - sB[qq]);
            ex1[qq] = expf(sc1[qq] - sB[qq]);
        }
#pragma unroll
        for (int qq = 0; qq < 8; qq++) red[qq] = ex0[qq] + ex1[qq];
#pragma unroll
        for (int off = 16; off > 0; off >>= 1)
#pragma unroll
            for (int qq = 0; qq < 8; qq++)
                red[qq] += __shfl_xor_sync(0xffffffffu, red[qq], off);
        if (lane == 0)
#pragma unroll
            for (int qq = 0; qq < 8; qq++) sRed[wid][qq] = red[qq];
        __syncthreads();
        if (tid < 8) {
            float v = 0.f;
#pragma unroll
            for (int w = 0; w < 8; w++) v += sRed[w][tid];
            sB[tid] = v;
        }
        __syncthreads();
#pragma unroll
        for (int qq = 0; qq < 8; qq++) {
            const float inv = 0.125f / sB[qq];
            padj0[qq] += ex0[qq] * inv;
            padj1[qq] += ex1[qq] * inv;
        }
        __syncthreads();
    }

    float rowv0[8], rowv1[8];
#pragma unroll
    for (int qq = 0; qq < 8; qq++) {
        float v0 = padj0[qq], v1 = padj1[qq];
        if (k0c == q0 + qq) v0 = 1.0f;
        if (k1c == q0 + qq) v1 = 1.0f;
        if (sTokQ[qq] == 0) { v0 = 0.0f; v1 = 0.0f; }
        rowv0[qq] = v0; rowv1[qq] = v1;
        const long long rb = ((long long)b * Sn + q0 + qq) * Sn;
        *(float2*)(adj + rb + k0c) = make_float2(v0, v1);
        uint32_t h, l;
        split_pair(v0, v1, h, l);
        const int qg = tid, g = qg >> 3, qi = qg & 7;
        const int p = ((qi & 3) << 1) | (qi >> 2);
        const long long m = (long long)b * Sn + q0 + qq;
        const long long o = m * (Sn / 2) + g * 8 + p;
        ajh[o] = h; ajl[o] = l;
    }

    float red[8];
#pragma unroll
    for (int qq = 0; qq < 8; qq++) red[qq] = rowv0[qq] + rowv1[qq];
#pragma unroll
    for (int off = 16; off > 0; off >>= 1)
#pragma unroll
        for (int qq = 0; qq < 8; qq++)
            red[qq] += __shfl_xor_sync(0xffffffffu, red[qq], off);
    if (lane == 0)
#pragma unroll
        for (int qq = 0; qq < 8; qq++) sRed[wid][qq] = red[qq];
    __syncthreads();
    if (tid < 8) {
        float v = 0.f;
#pragma unroll
        for (int w = 0; w < 8; w++) v += sRed[w][tid];
        denom[b * Sn + q0 + tid] = v + 1.0f;
    }
}

// ======================= small kernels =======================
__global__ void pool_kernel(const float* __restrict__ x, float* __restrict__ pool)
{
    const int b = blockIdx.y;
    const int d = blockIdx.x * 128 + threadIdx.x;
    const float* xp = x + (long long)b * Sn * Dn + d;
    float sm = 0.f, mx = -3.402823466e38f;
    for (int s = 0; s < Sn; s++) {
        const float v = xp[(long long)s * Dn];
        sm += v;
        mx = fmaxf(mx, v);
    }
    pool[b * (2 * Dn) + d] = sm * (1.f / Sn);
    pool[b * (2 * Dn) + Dn + d] = mx;
}

template <int ACT>
__global__ void rowmat_kernel(const float* __restrict__ in, const float* __restrict__ W,
                              const float* __restrict__ bias, float* __restrict__ out,
                              int K, int N)
{
    __shared__ float sIn[2 * Dn];
    const int b = blockIdx.y;
    const int n = blockIdx.x * 128 + threadIdx.x;
    for (int e = threadIdx.x; e < K; e += 128) sIn[e] = in[b * K + e];
    __syncthreads();
    float acc = bias[n];
#pragma unroll 4
    for (int k = 0; k < K; k++) acc += sIn[k] * W[(long long)k * N + n];
    if (ACT) acc = 1.f / (1.f + expf(-acc));
    out[b * N + n] = acc;
}

__global__ void final_kernel(float* __restrict__ x, const float* __restrict__ gate,
                             const float* __restrict__ gc)
{
    const int i = blockIdx.x * 256 + threadIdx.x;
    const int d = i % Dn;
    const int b = i / (Sn * Dn);
    x[i] += gate[b * Dn + d] * gc[b * Dn + d];
}

// ======================= launch =======================
extern "C" void kernel_launch(void* const* d_in, const int* in_sizes, int n_in,
                              void* d_out, int out_size)
{
    int o = (n_in >= 3 && in_sizes[2] == 1) ? 1 : 0;
    const float* inputs = (const float*)d_in[0];
    const int*   tok    = (const int*)d_in[1];
    const float* Wq  = (const float*)d_in[2 + o];
    const float* bq  = (const float*)d_in[3 + o];
    const float* Wk  = (const float*)d_in[4 + o];
    const float* bk  = (const float*)d_in[5 + o];
    const float* rel = (const float*)d_in[6 + o];
    const float* W0  = (const float*)d_in[7 + o];
    const float* b0  = (const float*)d_in[8 + o];
    const float* W1  = (const float*)d_in[9 + o];
    const float* b1  = (const float*)d_in[10 + o];
    const float* scw = (const float*)d_in[11 + o];
    const float* Wf  = (const float*)d_in[12 + o];
    const float* bf  = (const float*)d_in[13 + o];
    const float* Wfc = (const float*)d_in[14 + o];
    const float* bfc = (const float*)d_in[15 + o];
    const float* Wg  = (const float*)d_in[16 + o];
    const float* bg  = (const float*)d_in[17 + o];

    float* out = (float*)d_out;                      // (B,S,D)
    float* adj = out + (size_t)Bn * Sn * Dn;         // (B,S,S)

    float *q, *kt, *h0, *den, *pool, *gc, *gate;
    uint32_t *pah, *pal, *bwh, *bwl, *bxh, *bxl, *ajh, *ajl, *axh, *axl;
    cudaGetSymbolAddress((void**)&q, g_q);
    cudaGetSymbolAddress((void**)&kt, g_kt);
    cudaGetSymbolAddress((void**)&h0, g_h0);
    cudaGetSymbolAddress((void**)&den, g_denom);
    cudaGetSymbolAddress((void**)&pool, g_pool);
    cudaGetSymbolAddress((void**)&gc, g_gc);
    cudaGetSymbolAddress((void**)&gate, g_gate);
    cudaGetSymbolAddress((void**)&pah, g_pa_h);
    cudaGetSymbolAddress((void**)&pal, g_pa_l);
    cudaGetSymbolAddress((void**)&bwh, g_bw_h);
    cudaGetSymbolAddress((void**)&bwl, g_bw_l);
    cudaGetSymbolAddress((void**)&bxh, g_bx_h);
    cudaGetSymbolAddress((void**)&bxl, g_bx_l);
    cudaGetSymbolAddress((void**)&ajh, g_aj_h);
    cudaGetSymbolAddress((void**)&ajl, g_aj_l);
    cudaGetSymbolAddress((void**)&axh, g_ax_h);
    cudaGetSymbolAddress((void**)&axl, g_ax_l);

    cudaFuncSetAttribute(tc_gemm<0, 0, 1, 1, 0, 0, 1>, cudaFuncAttributeMaxDynamicSharedMemorySize, TC_SMEM);
    cudaFuncSetAttribute(tc_gemm<0, 0, 0, 0, 1, 0, 0>, cudaFuncAttributeMaxDynamicSharedMemorySize, TC_SMEM);
    cudaFuncSetAttribute(tc_gemm<1, 1, 1, 0, 0, 0, 0>, cudaFuncAttributeMaxDynamicSharedMemorySize, TC_SMEM);
    cudaFuncSetAttribute(tc_gemm<1, 1, 1, 0, 0, 1, 0>, cudaFuncAttributeMaxDynamicSharedMemorySize, TC_SMEM);
    cudaFuncSetAttribute(tc_gemm<0, 0, 1, 0, 0, 0, 0>, cudaFuncAttributeMaxDynamicSharedMemorySize, TC_SMEM);

    const long long WOFF = 768LL * 384;              // per-weight packed plane stride
    const dim3 gFlat(Dn / 128, (Bn * Sn) / 128, 1);  // 6 x 64
    const dim3 gQK(Dn / 128, (Bn * Sn) / 128, 2);
    const dim3 gBmm(Dn / 128, Sn / 128, Bn);         // 6 x 4 x 16

    // [1] pack A(inputs) for projections
    packA<<<(8192 * 384) / 256, 256>>>(inputs, pah, pal, Dn);
    // [2] pack B: all 5 weights in one launch (Wq, Wk, W0, W1, Wf)
    packBT5<<<dim3(Dn / 64, Dn / 16, 5), 256>>>(Wq, Wk, W0, W1, Wf,
                                                bwh, bwl, WOFF, Dn, Dn);
    // [3] QK projections (dual); K output written TRANSPOSED -> kT directly
    tc_gemm<0, 0, 1, 1, 0, 0, 1><<<gQK, 256, TC_SMEM>>>(
        pah, pal, bwh, bwl, bq, nullptr, q, nullptr, nullptr,
        bwh + WOFF, bwl + WOFF, bk, kt, nullptr, nullptr, Dn, Dn, 0, 0, 0, 0);
    // [4] fused attention (coalesced kT) -> adj + packed planes, denom  (ncu slot)
    attn_kernel<<<Bn * (Sn / 8), 256>>>(q, kt, tok, rel, adj, den, ajh, ajl);
    // [5] pack B: inputs transposed per batch (for bmm0)
    packBTX<<<dim3(Dn / 64, Sn / 16, Bn), 256>>>(inputs, (long long)Sn * Dn,
                                                 bxh, bxl, 768LL * 256, Sn, Dn);
    // [6] bmm0: ax = adj @ inputs  (packed output)
    tc_gemm<0, 0, 0, 0, 1, 0, 0><<<gBmm, 256, TC_SMEM>>>(
        ajh, ajl, bxh, bxl, nullptr, nullptr, nullptr, axh, axl,
        nullptr, nullptr, nullptr, nullptr, nullptr, nullptr, Dn, Sn,
        512LL * 256, 768LL * 256, 0, 512LL * 384);
    // [7] wgemm0: h0 = relu((ax@W0+b0)/den)
    tc_gemm<1, 1, 1, 0, 0, 0, 0><<<gFlat, 256, TC_SMEM>>>(
        axh, axl, bwh + 2 * WOFF, bwl + 2 * WOFF, b0, den, h0, nullptr, nullptr,
        nullptr, nullptr, nullptr, nullptr, nullptr, nullptr, Dn, Dn, 0, 0, 0, 0);
    // [8] pack B: h0 transposed per batch (for bmm1)
    packBTX<<<dim3(Dn / 64, Sn / 16, Bn), 256>>>(h0, (long long)Sn * Dn,
                                                 bxh, bxl, 768LL * 256, Sn, Dn);
    // [9] bmm1
    tc_gemm<0, 0, 0, 0, 1, 0, 0><<<gBmm, 256, TC_SMEM>>>(
        ajh, ajl, bxh, bxl, nullptr, nullptr, nullptr, axh, axl,
        nullptr, nullptr, nullptr, nullptr, nullptr, nullptr, Dn, Sn,
        512LL * 256, 768LL * 256, 0, 512LL * 384);
    // [10] wgemm1 + fused combine -> packed combined planes
    tc_gemm<1, 1, 1, 0, 0, 1, 0><<<gFlat, 256, TC_SMEM>>>(
        axh, axl, bwh + 3 * WOFF, bwl + 3 * WOFF, b1, den, nullptr, pah, pal,
        nullptr, nullptr, nullptr, nullptr, h0, scw, Dn, Dn, 0, 0, 0, 0);
    // [11] Wf GEMM -> out
    tc_gemm<0, 0, 1, 0, 0, 0, 0><<<gFlat, 256, TC_SMEM>>>(
        pah, pal, bwh + 4 * WOFF, bwl + 4 * WOFF, bf, nullptr, out, nullptr, nullptr,
        nullptr, nullptr, nullptr, nullptr, nullptr, nullptr, Dn, Dn, 0, 0, 0, 0);

    // global context gating
    pool_kernel<<<dim3(Dn / 128, Bn), 128>>>(out, pool);
    rowmat_kernel<0><<<dim3(Dn / 128, Bn), 128>>>(pool, Wfc, bfc, gc, 2 * Dn, Dn);
    rowmat_kernel<1><<<dim3(Dn / 128, Bn), 128>>>(gc, Wg, bg, gate, Dn, Dn);
    final_kernel<<<(Bn * Sn * Dn) / 256, 256>>>(out, gate, gc);
}